// round 3
// baseline (speedup 1.0000x reference)
#include <cuda_runtime.h>
#include <math.h>

// Kalman filter one-step-ahead predictions.
// B=512, T=256, S=32, M=4.
// Warp-per-batch, register-resident covariance (lane j holds column j == row j
// of the symmetric P). Launch shape: 128 blocks x 128 threads = 4 warps/block,
// one warp per SMSP (wid%4 mapping), 4 batches per block. Constants F/Q/H/R in
// block-shared; per-warp private scratch for the X=P_u*F^T transpose, PH^T and
// whitened-z vectors. Packed fma.rn.f32x2 for the big GEMMs.

#define Bn 512
#define Tn 256
#define Sn 32
#define Mn 4
#define WPB 4   // warps (batches) per block

using u64 = unsigned long long;

__device__ __forceinline__ u64 pack2(float lo, float hi) {
    u64 r; asm("mov.b64 %0,{%1,%2};" : "=l"(r) : "f"(lo), "f"(hi)); return r;
}
__device__ __forceinline__ void unpack2(u64 v, float& lo, float& hi) {
    asm("mov.b64 {%0,%1},%2;" : "=f"(lo), "=f"(hi) : "l"(v));
}
__device__ __forceinline__ u64 ffma2(u64 a, u64 b, u64 c) {
    u64 d; asm("fma.rn.f32x2 %0,%1,%2,%3;" : "=l"(d) : "l"(a), "l"(b), "l"(c)); return d;
}

__global__ __launch_bounds__(32 * WPB) void kalman_kernel(
    const float* __restrict__ obs,       // [B,T,M]
    const float* __restrict__ Fm,        // [S,S]
    const float* __restrict__ Qm,        // [S,S]
    const float* __restrict__ Hm,        // [M,S]
    const float* __restrict__ Rm,        // [M,M]
    const float* __restrict__ init_mean, // [B,S]
    const float* __restrict__ init_cov,  // [B,S,S]
    float* __restrict__ out)
{
    const int tid  = threadIdx.x;
    const int wid  = tid >> 5;
    const int lane = tid & 31;
    const int b    = blockIdx.x * WPB + wid;

    // ---- common constants (read-only after init) ----
    // F pairs: float view fv[l*36+i] = F[i][l]; u64 view [l*18+c] = (F[2c][l],F[2c+1][l])
    __shared__ __align__(16) u64 sFTp[Sn * 18];
    // Q column pairs: float view [j*36+i] = Q[i][j]
    __shared__ __align__(16) u64 sQp[Sn * 18];
    // H: float view [l*4+q] = H[q][l]
    __shared__ __align__(16) u64 sHTp[Sn * 2];
    __shared__ float sR16[16];

    // ---- per-warp scratch ----
    __shared__ __align__(16) u64   sPHp[WPB][Sn * 2];   // PH^T rows (4 floats per row)
    __shared__ __align__(16) float sX  [WPB][Sn * 36];  // X = P_u*F^T rows, padded
    __shared__ __align__(16) float sZ  [WPB][Sn * 4];   // whitened z per row

    {
        float* fv = (float*)sFTp;
        float* qv = (float*)sQp;
        for (int idx = tid; idx < Sn * Sn; idx += 32 * WPB) {
            int i = idx >> 5, l = idx & 31;
            fv[l * 36 + i] = Fm[idx];   // F[i][l]
            qv[l * 36 + i] = Qm[idx];   // Q[i][l] (symmetric use as column l)
        }
        float* hv = (float*)sHTp;
        for (int idx = tid; idx < Mn * Sn; idx += 32 * WPB) {
            int q = idx >> 5, l = idx & 31;
            hv[l * 4 + q] = Hm[idx];
        }
        if (tid < 16) sR16[tid] = Rm[tid];
    }

    // per-lane state: P column `lane` (== row, symmetric), mean elem, H column
    float p[Sn];
#pragma unroll
    for (int i = 0; i < Sn; ++i)
        p[i] = init_cov[(size_t)b * (Sn * Sn) + i * Sn + lane];
    float mloc = init_mean[b * Sn + lane];
    float Hl0 = Hm[0 * Sn + lane], Hl1 = Hm[1 * Sn + lane];
    float Hl2 = Hm[2 * Sn + lane], Hl3 = Hm[3 * Sn + lane];

    __syncthreads();  // constants visible; warps independent afterwards

    u64*   wPH = sPHp[wid];
    float* wX  = sX[wid];
    float* wZ  = sZ[wid];

    const float* yb = obs + (size_t)b * (Tn * Mn);
    float* out_means = out;                               // [T,B,M]
    float* out_covs  = out + (size_t)Tn * Bn * Mn;        // [T,B,M,M]

    float4 yn = *(const float4*)yb;  // prefetch y_0

#pragma unroll 1
    for (int t = 0; t < Tn; ++t) {
        float4 yv = yn;
        int tnext = (t + 1 < Tn) ? (t + 1) : (Tn - 1);
        yn = *(const float4*)(yb + 4 * tnext);

        // ---- measurement mean mm = H * m (butterfly reduce, all lanes get it)
        float c0 = Hl0 * mloc, c1 = Hl1 * mloc, c2 = Hl2 * mloc, c3 = Hl3 * mloc;
#pragma unroll
        for (int s = 16; s >= 1; s >>= 1) {
            c0 += __shfl_xor_sync(0xffffffffu, c0, s);
            c1 += __shfl_xor_sync(0xffffffffu, c1, s);
            c2 += __shfl_xor_sync(0xffffffffu, c2, s);
            c3 += __shfl_xor_sync(0xffffffffu, c3, s);
        }
        if (lane == 0)
            *(float4*)&out_means[((size_t)t * Bn + b) * 4] = make_float4(c0, c1, c2, c3);
        float r0 = yv.x - c0, r1 = yv.y - c1, r2 = yv.z - c2, r3 = yv.w - c3;

        // ---- phtt = row `lane` of P*H^T  (packed f32x2)
        u64 ph2a = 0ull, ph2b = 0ull;
#pragma unroll
        for (int l = 0; l < Sn; ++l) {
            u64 ps = pack2(p[l], p[l]);
            ulonglong2 h = *(const ulonglong2*)&sHTp[l * 2];
            ph2a = ffma2(ps, h.x, ph2a);
            ph2b = ffma2(ps, h.y, ph2b);
        }
        float ph0, ph1, phh2, ph3;
        unpack2(ph2a, ph0, ph1);
        unpack2(ph2b, phh2, ph3);
        wPH[lane * 2 + 0] = ph2a;
        wPH[lane * 2 + 1] = ph2b;
        __syncwarp();

        // ---- S = H*(PH^T) + R : lane index q*4+r (dup for lanes>=16)
        int q = (lane >> 2) & 3, r = lane & 3;
        float sv = sR16[(q << 2) | r];
        {
            const float* hf = (const float*)sHTp;
            const float* pf = (const float*)wPH;
#pragma unroll 8
            for (int l = 0; l < Sn; ++l)
                sv = fmaf(hf[l * 4 + q], pf[l * 4 + r], sv);
        }
        if (lane < 16)
            out_covs[((size_t)t * Bn + b) * 16 + lane] = sv;  // mc_t == S_t

        if (t == Tn - 1) break;

        // ---- broadcast S, redundant 4x4 Cholesky in every lane
        float s00 = __shfl_sync(0xffffffffu, sv, 0);
        float s10 = __shfl_sync(0xffffffffu, sv, 4);
        float s11 = __shfl_sync(0xffffffffu, sv, 5);
        float s20 = __shfl_sync(0xffffffffu, sv, 8);
        float s21 = __shfl_sync(0xffffffffu, sv, 9);
        float s22 = __shfl_sync(0xffffffffu, sv, 10);
        float s30 = __shfl_sync(0xffffffffu, sv, 12);
        float s31 = __shfl_sync(0xffffffffu, sv, 13);
        float s32 = __shfl_sync(0xffffffffu, sv, 14);
        float s33 = __shfl_sync(0xffffffffu, sv, 15);
        float l00 = sqrtf(s00), i0 = 1.f / l00;
        float L10 = s10 * i0, L20 = s20 * i0, L30 = s30 * i0;
        float l11 = sqrtf(s11 - L10 * L10), i1 = 1.f / l11;
        float L21 = (s21 - L20 * L10) * i1;
        float L31 = (s31 - L30 * L10) * i1;
        float l22 = sqrtf(s22 - L20 * L20 - L21 * L21), i2 = 1.f / l22;
        float L32 = (s32 - L30 * L20 - L31 * L21) * i2;
        float l33 = sqrtf(s33 - L30 * L30 - L31 * L31 - L32 * L32), i3 = 1.f / l33;

        // ---- whitened z (forward solve) and gain row (back solve), per lane
        float z0 = ph0 * i0;
        float z1 = (ph1 - L10 * z0) * i1;
        float z2 = (phh2 - L20 * z0 - L21 * z1) * i2;
        float z3 = (ph3 - L30 * z0 - L31 * z1 - L32 * z2) * i3;
        float k3 = z3 * i3;
        float k2 = (z2 - L32 * k3) * i2;
        float k1 = (z1 - L21 * k2 - L31 * k3) * i1;
        float k0 = (z0 - L10 * k1 - L20 * k2 - L30 * k3) * i0;

        *(float4*)&wZ[lane * 4] = make_float4(z0, z1, z2, z3);
        __syncwarp();

        // ---- mean update
        mloc = fmaf(k0, r0, fmaf(k1, r1, fmaf(k2, r2, fmaf(k3, r3, mloc))));

        // ---- covariance downdate: p[i] -= z_i . z_lane  (bitwise symmetric)
#pragma unroll
        for (int i = 0; i < Sn; ++i) {
            float4 zi = *(const float4*)&wZ[i * 4];
            float d = zi.x * z0;
            d = fmaf(zi.y, z1, d);
            d = fmaf(zi.z, z2, d);
            d = fmaf(zi.w, z3, d);
            p[i] -= d;
        }

        // ---- GEMM1: X row `lane` = p . F^T : x[m] = sum_l p[l]*F[m][l]
        u64 x2[16];
#pragma unroll
        for (int c = 0; c < 16; ++c) x2[c] = 0ull;
#pragma unroll
        for (int l = 0; l < Sn; ++l) {
            u64 ps = pack2(p[l], p[l]);
            const ulonglong2* fr = (const ulonglong2*)&sFTp[l * 18];
#pragma unroll
            for (int c2 = 0; c2 < 8; ++c2) {
                ulonglong2 f = fr[c2];
                x2[2 * c2 + 0] = ffma2(ps, f.x, x2[2 * c2 + 0]);
                x2[2 * c2 + 1] = ffma2(ps, f.y, x2[2 * c2 + 1]);
            }
        }
#pragma unroll
        for (int c = 0; c < 16; ++c)
            *(u64*)&wX[lane * 36 + 2 * c] = x2[c];
        __syncwarp();

        // ---- mean predict: mp[lane] = sum_l F[lane][l] * m_u[l]
        float mp = 0.f;
        {
            const float* fv = (const float*)sFTp;
#pragma unroll 8
            for (int l = 0; l < Sn; ++l) {
                float ml = __shfl_sync(0xffffffffu, mloc, l);
                mp = fmaf(fv[l * 36 + lane], ml, mp);
            }
        }

        // ---- GEMM2: P_new column `lane` = F * X[:,lane] + Q[:,lane]
        u64 a2[16];
        {
            const ulonglong2* qr = (const ulonglong2*)&sQp[lane * 18];
#pragma unroll
            for (int c2 = 0; c2 < 8; ++c2) {
                ulonglong2 qq = qr[c2];
                a2[2 * c2 + 0] = qq.x;
                a2[2 * c2 + 1] = qq.y;
            }
        }
#pragma unroll 4
        for (int k = 0; k < Sn; ++k) {
            float xv = wX[k * 36 + lane];
            u64 xs = pack2(xv, xv);
            const ulonglong2* fr = (const ulonglong2*)&sFTp[k * 18];
#pragma unroll
            for (int c2 = 0; c2 < 8; ++c2) {
                ulonglong2 f = fr[c2];
                a2[2 * c2 + 0] = ffma2(xs, f.x, a2[2 * c2 + 0]);
                a2[2 * c2 + 1] = ffma2(xs, f.y, a2[2 * c2 + 1]);
            }
        }
#pragma unroll
        for (int c = 0; c < 16; ++c)
            unpack2(a2[c], p[2 * c], p[2 * c + 1]);

        mloc = mp;
        __syncwarp();
    }
}

extern "C" void kernel_launch(void* const* d_in, const int* in_sizes, int n_in,
                              void* d_out, int out_size)
{
    const float* obs       = (const float*)d_in[0];
    const float* Fm        = (const float*)d_in[1];
    const float* Qm        = (const float*)d_in[2];
    const float* Hm        = (const float*)d_in[3];
    const float* Rm        = (const float*)d_in[4];
    const float* init_mean = (const float*)d_in[5];
    const float* init_cov  = (const float*)d_in[6];
    float* out = (float*)d_out;

    kalman_kernel<<<Bn / WPB, 32 * WPB>>>(obs, Fm, Qm, Hm, Rm, init_mean, init_cov, out);
}

// round 4
// speedup vs baseline: 1.2592x; 1.2592x over previous
#include <cuda_runtime.h>
#include <math.h>

// Kalman filter one-step-ahead predictions.
// B=512, T=256, S=32, M=4.
// Warp-per-batch (32-thread blocks x 512), register-resident symmetric P
// (lane j holds column j == row j). Packed fma.rn.f32x2 GEMMs with
// uniform-broadcast LDS.128 streaming of F. Vectorized S / mean-predict paths.

#define Bn 512
#define Tn 256
#define Sn 32
#define Mn 4

using u64 = unsigned long long;

__device__ __forceinline__ u64 pack2(float lo, float hi) {
    u64 r; asm("mov.b64 %0,{%1,%2};" : "=l"(r) : "f"(lo), "f"(hi)); return r;
}
__device__ __forceinline__ void unpack2(u64 v, float& lo, float& hi) {
    asm("mov.b64 {%0,%1},%2;" : "=f"(lo), "=f"(hi) : "l"(v));
}
__device__ __forceinline__ u64 ffma2(u64 a, u64 b, u64 c) {
    u64 d; asm("fma.rn.f32x2 %0,%1,%2,%3;" : "=l"(d) : "l"(a), "l"(b), "l"(c)); return d;
}

__global__ __launch_bounds__(32) void kalman_kernel(
    const float* __restrict__ obs,       // [B,T,M]
    const float* __restrict__ Fm,        // [S,S]
    const float* __restrict__ Qm,        // [S,S]
    const float* __restrict__ Hm,        // [M,S]
    const float* __restrict__ Rm,        // [M,M]
    const float* __restrict__ init_mean, // [B,S]
    const float* __restrict__ init_cov,  // [B,S,S]
    float* __restrict__ out)
{
    const int b    = blockIdx.x;
    const int lane = threadIdx.x;

    // F column pairs: float view fv[l*36+i] = F[i][l]
    __shared__ __align__(16) u64 sFTp[Sn * 18];
    // Q column pairs: float view [j*36+i] = Q[i][j]
    __shared__ __align__(16) u64 sQp[Sn * 18];
    // H per-l quads: float view [l*4+q] = H[q][l]  (for the PH GEMM)
    __shared__ __align__(16) u64 sHTp[Sn * 2];
    // H row-major pairs: float view hr[q*34+l] = H[q][l]  (for S-compute)
    __shared__ __align__(16) u64 sHR[4 * 17];
    // F row-major pairs: float view fr[j*34+l] = F[j][l]  (for mean predict)
    __shared__ __align__(16) u64 sFR[Sn * 17];
    // PH^T row-major: float view pht[r*34+l] = (P H^T)[l][r]
    __shared__ __align__(16) u64 sPHT[4 * 17];
    // X = P_u * F^T rows, padded to 36 floats per row
    __shared__ __align__(16) float sX[Sn * 36];
    // whitened z per row
    __shared__ __align__(16) float sZ[Sn * 4];
    // updated mean pairs: float view [16 u64]
    __shared__ __align__(16) u64 sMu[16];
    __shared__ float sR16[16];

    {
        float* fv  = (float*)sFTp;
        float* qv  = (float*)sQp;
        float* frf = (float*)sFR;
        for (int idx = lane; idx < Sn * Sn; idx += 32) {
            int i = idx >> 5, l = idx & 31;
            float f = Fm[idx];
            fv [l * 36 + i] = f;        // F[i][l] column-pair layout
            frf[i * 34 + l] = f;        // F[i][l] row-pair layout
            qv [l * 36 + i] = Qm[idx];  // Q column pairs (symmetric)
        }
        float* hv  = (float*)sHTp;
        float* hrf = (float*)sHR;
        for (int idx = lane; idx < Mn * Sn; idx += 32) {
            int q = idx >> 5, l = idx & 31;
            float h = Hm[idx];
            hv [l * 4 + q]  = h;
            hrf[q * 34 + l] = h;
        }
        if (lane < 16) sR16[lane] = Rm[lane];
    }

    // per-lane state: P column `lane` (== row), mean element, H column
    float p[Sn];
#pragma unroll
    for (int i = 0; i < Sn; ++i)
        p[i] = init_cov[(size_t)b * (Sn * Sn) + i * Sn + lane];
    float mloc = init_mean[b * Sn + lane];
    float Hl0 = Hm[0 * Sn + lane], Hl1 = Hm[1 * Sn + lane];
    float Hl2 = Hm[2 * Sn + lane], Hl3 = Hm[3 * Sn + lane];
    __syncwarp();

    const float* yb = obs + (size_t)b * (Tn * Mn);
    float* out_means = out;                               // [T,B,M]
    float* out_covs  = out + (size_t)Tn * Bn * Mn;        // [T,B,M,M]

    float4 yn = *(const float4*)yb;  // prefetch y_0
    float* phtF = (float*)sPHT;
    float* muF  = (float*)sMu;

#pragma unroll 1
    for (int t = 0; t < Tn; ++t) {
        float4 yv = yn;
        int tnext = (t + 1 < Tn) ? (t + 1) : (Tn - 1);
        yn = *(const float4*)(yb + 4 * tnext);

        // ---- phtt = row `lane` of P*H^T (packed) ; butterflies interleave
        u64 ph2a = 0ull, ph2b = 0ull;
#pragma unroll
        for (int l = 0; l < Sn; ++l) {
            u64 ps = pack2(p[l], p[l]);
            ulonglong2 h = *(const ulonglong2*)&sHTp[l * 2];
            ph2a = ffma2(ps, h.x, ph2a);
            ph2b = ffma2(ps, h.y, ph2b);
        }
        // measurement mean mm = H * m (butterfly reduce, all lanes)
        float c0 = Hl0 * mloc, c1 = Hl1 * mloc, c2 = Hl2 * mloc, c3 = Hl3 * mloc;
#pragma unroll
        for (int s = 16; s >= 1; s >>= 1) {
            c0 += __shfl_xor_sync(0xffffffffu, c0, s);
            c1 += __shfl_xor_sync(0xffffffffu, c1, s);
            c2 += __shfl_xor_sync(0xffffffffu, c2, s);
            c3 += __shfl_xor_sync(0xffffffffu, c3, s);
        }
        float ph0, ph1, phh2, ph3;
        unpack2(ph2a, ph0, ph1);
        unpack2(ph2b, phh2, ph3);
        // store PH^T transposed rows for vectorized S
        phtF[0 * 34 + lane] = ph0;
        phtF[1 * 34 + lane] = ph1;
        phtF[2 * 34 + lane] = phh2;
        phtF[3 * 34 + lane] = ph3;

        if (lane == 0)
            *(float4*)&out_means[((size_t)t * Bn + b) * 4] = make_float4(c0, c1, c2, c3);
        float r0 = yv.x - c0, r1 = yv.y - c1, r2 = yv.z - c2, r3 = yv.w - c3;
        __syncwarp();

        // ---- S = H*(PH^T) + R : lane (q,r), duplicated for lanes>=16
        int q = (lane >> 2) & 3, r = lane & 3;
        float sv;
        {
            u64 acc2 = 0ull;
            const u64* hq = &sHR [q * 17];
            const u64* pr = &sPHT[r * 17];
#pragma unroll
            for (int c = 0; c < 16; ++c)
                acc2 = ffma2(hq[c], pr[c], acc2);
            float alo, ahi; unpack2(acc2, alo, ahi);
            sv = sR16[(q << 2) | r] + (alo + ahi);
        }
        if (lane < 16)
            out_covs[((size_t)t * Bn + b) * 16 + lane] = sv;  // mc_t == S_t

        if (t == Tn - 1) break;

        // ---- broadcast S, redundant 4x4 Cholesky in every lane
        float s00 = __shfl_sync(0xffffffffu, sv, 0);
        float s10 = __shfl_sync(0xffffffffu, sv, 4);
        float s11 = __shfl_sync(0xffffffffu, sv, 5);
        float s20 = __shfl_sync(0xffffffffu, sv, 8);
        float s21 = __shfl_sync(0xffffffffu, sv, 9);
        float s22 = __shfl_sync(0xffffffffu, sv, 10);
        float s30 = __shfl_sync(0xffffffffu, sv, 12);
        float s31 = __shfl_sync(0xffffffffu, sv, 13);
        float s32 = __shfl_sync(0xffffffffu, sv, 14);
        float s33 = __shfl_sync(0xffffffffu, sv, 15);
        float l00 = sqrtf(s00), i0 = 1.f / l00;
        float L10 = s10 * i0, L20 = s20 * i0, L30 = s30 * i0;
        float l11 = sqrtf(s11 - L10 * L10), i1 = 1.f / l11;
        float L21 = (s21 - L20 * L10) * i1;
        float L31 = (s31 - L30 * L10) * i1;
        float l22 = sqrtf(s22 - L20 * L20 - L21 * L21), i2 = 1.f / l22;
        float L32 = (s32 - L30 * L20 - L31 * L21) * i2;
        float l33 = sqrtf(s33 - L30 * L30 - L31 * L31 - L32 * L32), i3 = 1.f / l33;

        // ---- whitened z (forward) and gain row (back solve), per lane
        float z0 = ph0 * i0;
        float z1 = (ph1 - L10 * z0) * i1;
        float z2 = (phh2 - L20 * z0 - L21 * z1) * i2;
        float z3 = (ph3 - L30 * z0 - L31 * z1 - L32 * z2) * i3;
        float k3 = z3 * i3;
        float k2 = (z2 - L32 * k3) * i2;
        float k1 = (z1 - L21 * k2 - L31 * k3) * i1;
        float k0 = (z0 - L10 * k1 - L20 * k2 - L30 * k3) * i0;

        *(float4*)&sZ[lane * 4] = make_float4(z0, z1, z2, z3);
        __syncwarp();

        // ---- mean update + publish m_u pairs for mean-predict
        mloc = fmaf(k0, r0, fmaf(k1, r1, fmaf(k2, r2, fmaf(k3, r3, mloc))));
        muF[lane] = mloc;

        // ---- covariance downdate: p[i] -= z_i . z_lane (bitwise symmetric)
#pragma unroll
        for (int i = 0; i < Sn; ++i) {
            float4 zi = *(const float4*)&sZ[i * 4];
            float d = zi.x * z0;
            d = fmaf(zi.y, z1, d);
            d = fmaf(zi.z, z2, d);
            d = fmaf(zi.w, z3, d);
            p[i] -= d;
        }

        // ---- GEMM1: X row `lane` = p . F^T
        u64 x2[16];
#pragma unroll
        for (int c = 0; c < 16; ++c) x2[c] = 0ull;
#pragma unroll
        for (int l = 0; l < Sn; ++l) {
            u64 ps = pack2(p[l], p[l]);
            const ulonglong2* fr = (const ulonglong2*)&sFTp[l * 18];
#pragma unroll
            for (int c2 = 0; c2 < 8; ++c2) {
                ulonglong2 f = fr[c2];
                x2[2 * c2 + 0] = ffma2(ps, f.x, x2[2 * c2 + 0]);
                x2[2 * c2 + 1] = ffma2(ps, f.y, x2[2 * c2 + 1]);
            }
        }
#pragma unroll
        for (int c = 0; c < 16; ++c)
            *(u64*)&sX[lane * 36 + 2 * c] = x2[c];
        __syncwarp();

        // ---- mean predict: mp[lane] = sum_l F[lane][l] * m_u[l] (vectorized)
        float mp;
        {
            u64 acc2 = 0ull;
            const u64* frw = &sFR[lane * 17];
#pragma unroll
            for (int c = 0; c < 16; ++c)
                acc2 = ffma2(frw[c], sMu[c], acc2);
            float alo, ahi; unpack2(acc2, alo, ahi);
            mp = alo + ahi;
        }

        // ---- GEMM2: P_new column `lane` = F * X[:,lane] + Q[:,lane]
        u64 a2[16];
        {
            const ulonglong2* qr = (const ulonglong2*)&sQp[lane * 18];
#pragma unroll
            for (int c2 = 0; c2 < 8; ++c2) {
                ulonglong2 qq = qr[c2];
                a2[2 * c2 + 0] = qq.x;
                a2[2 * c2 + 1] = qq.y;
            }
        }
#pragma unroll 8
        for (int k = 0; k < Sn; ++k) {
            float xv = sX[k * 36 + lane];
            u64 xs = pack2(xv, xv);
            const ulonglong2* fr = (const ulonglong2*)&sFTp[k * 18];
#pragma unroll
            for (int c2 = 0; c2 < 8; ++c2) {
                ulonglong2 f = fr[c2];
                a2[2 * c2 + 0] = ffma2(xs, f.x, a2[2 * c2 + 0]);
                a2[2 * c2 + 1] = ffma2(xs, f.y, a2[2 * c2 + 1]);
            }
        }
#pragma unroll
        for (int c = 0; c < 16; ++c)
            unpack2(a2[c], p[2 * c], p[2 * c + 1]);

        mloc = mp;
        __syncwarp();
    }
}

extern "C" void kernel_launch(void* const* d_in, const int* in_sizes, int n_in,
                              void* d_out, int out_size)
{
    const float* obs       = (const float*)d_in[0];
    const float* Fm        = (const float*)d_in[1];
    const float* Qm        = (const float*)d_in[2];
    const float* Hm        = (const float*)d_in[3];
    const float* Rm        = (const float*)d_in[4];
    const float* init_mean = (const float*)d_in[5];
    const float* init_cov  = (const float*)d_in[6];
    float* out = (float*)d_out;

    kalman_kernel<<<Bn, 32>>>(obs, Fm, Qm, Hm, Rm, init_mean, init_cov, out);
}